// round 9
// baseline (speedup 1.0000x reference)
#include <cuda_runtime.h>
#include <cuda_fp16.h>
#include <cstdint>

#define EMB 128
#define NR 6
#define NS 7
#define NB 8
#define MAXE 100000
#define EPAD 100096            // MAXE rounded up to 256 (100096 = 391*256)
#define MAXL 500000
#define PITCH 136              // fp16 elements per smem row (272B, conflict-free ldmatrix)

// ---------------- device scratch ----------------
static __device__ float g_P[MAXE * 56];                  // [e][s*8+b]
static __device__ __half g_Yh[(size_t)MAXE * 1024];      // [e][i*8+j]  (fp16)
static __device__ __half g_Ah[(size_t)EPAD * 128];       // m (fp16)
static __device__ __half g_Bh[1152 * 128];               // B[n][k]
static __device__ float g_sbf[(size_t)MAXL * 8];         // per-triplet sbf
// dst-bucket CSR
static __device__ int g_cnt[MAXE];
static __device__ int g_off[MAXE];
static __device__ int g_cur[MAXE];
static __device__ int g_bsum[128];
static __device__ int g_order[MAXL];

// ---------------- helpers ----------------
__device__ __forceinline__ uint32_t smem_u32(const void* p) {
    uint32_t a;
    asm("{ .reg .u64 t; cvta.to.shared.u64 t, %1; cvt.u32.u64 %0, t; }" : "=r"(a) : "l"(p));
    return a;
}
__device__ __forceinline__ void ldsm4(uint32_t* r, uint32_t addr) {
    asm volatile("ldmatrix.sync.aligned.m8n8.x4.shared.b16 {%0,%1,%2,%3}, [%4];"
                 : "=r"(r[0]), "=r"(r[1]), "=r"(r[2]), "=r"(r[3]) : "r"(addr));
}
__device__ __forceinline__ void mma16816(float* c, const uint32_t* a, const uint32_t* b) {
    asm volatile(
        "mma.sync.aligned.m16n8k16.row.col.f32.f16.f16.f32 "
        "{%0,%1,%2,%3}, {%4,%5,%6,%7}, {%8,%9}, {%0,%1,%2,%3};"
        : "+f"(c[0]), "+f"(c[1]), "+f"(c[2]), "+f"(c[3])
        : "r"(a[0]), "r"(a[1]), "r"(a[2]), "r"(a[3]), "r"(b[0]), "r"(b[1]));
}

// ---------------- prep kernels ----------------
__global__ void prep_m(const float* __restrict__ m, int E) {
    int idx = blockIdx.x * blockDim.x + threadIdx.x;
    if (idx >= EPAD * 128) return;
    int e = idx >> 7;
    float v = (e < E) ? m[idx] : 0.f;
    g_Ah[idx] = __float2half_rn(v);
}

__global__ void prep_B(const float* __restrict__ W_bilin, const float* __restrict__ W_m) {
    int idx = blockIdx.x * blockDim.x + threadIdx.x;
    if (idx >= 1152 * 128) return;
    int n = idx >> 7, k = idx & 127;
    float v = (n < 1024) ? W_bilin[idx] : W_m[k * EMB + (n - 1024)];
    g_Bh[idx] = __float2half_rn(v);
}

__global__ void prep_P(const float* __restrict__ rbf,
                       const float* __restrict__ W_sbf, int E) {
    int idx = blockIdx.x * blockDim.x + threadIdx.x;  // E*8
    if (idx >= E * 8) return;
    int e = idx >> 3, b = idx & 7;
    float rb[NR];
#pragma unroll
    for (int r = 0; r < NR; ++r) rb[r] = rbf[e * NR + r];
#pragma unroll
    for (int s = 0; s < NS; ++s) {
        float acc = 0.f;
#pragma unroll
        for (int r = 0; r < NR; ++r) acc += rb[r] * W_sbf[(s * NR + r) * NB + b];
        g_P[e * 56 + s * 8 + b] = acc;
    }
}

// ---------------- dst-bucket CSR build ----------------
__global__ void zero_cnt(int E) {
    int i = blockIdx.x * blockDim.x + threadIdx.x;
    if (i < E) g_cnt[i] = 0;
}
__global__ void count_k(const int* __restrict__ lg_dst, int L) {
    int l = blockIdx.x * blockDim.x + threadIdx.x;
    if (l < L) atomicAdd(&g_cnt[lg_dst[l]], 1);
}
__global__ void scan1(int E) {
    __shared__ int s[1024];
    int t = threadIdx.x, i = blockIdx.x * 1024 + t;
    int v = (i < E) ? g_cnt[i] : 0;
    s[t] = v;
    __syncthreads();
    for (int d = 512; d > 0; d >>= 1) {
        if (t < d) s[t] += s[t + d];
        __syncthreads();
    }
    if (t == 0) g_bsum[blockIdx.x] = s[0];
}
__global__ void scan2(int nblk) {
    __shared__ int s[128];
    int t = threadIdx.x;
    int v = (t < nblk) ? g_bsum[t] : 0;
    s[t] = v;
    __syncthreads();
#pragma unroll
    for (int d = 1; d < 128; d <<= 1) {
        int x = (t >= d) ? s[t - d] : 0;
        __syncthreads();
        s[t] += x;
        __syncthreads();
    }
    if (t < nblk) g_bsum[t] = s[t] - v;
}
__global__ void scan3(int E) {
    __shared__ int s[1024];
    int t = threadIdx.x, i = blockIdx.x * 1024 + t;
    int v = (i < E) ? g_cnt[i] : 0;
    s[t] = v;
    __syncthreads();
    for (int d = 1; d < 1024; d <<= 1) {
        int x = (t >= d) ? s[t - d] : 0;
        __syncthreads();
        s[t] += x;
        __syncthreads();
    }
    if (i < E) {
        int off = g_bsum[blockIdx.x] + s[t] - v;
        g_off[i] = off;
        g_cur[i] = off;
    }
}
__global__ void scatter_k(const int* __restrict__ lg_dst, int L) {
    int l = blockIdx.x * blockDim.x + threadIdx.x;
    if (l < L) {
        int pos = atomicAdd(&g_cur[lg_dst[l]], 1);
        g_order[pos] = l;
    }
}

// ---------------- sbf kernel: thread = (triplet, b) ----------------
__global__ __launch_bounds__(256) void sbf_kernel(
    const float* __restrict__ o, const int* __restrict__ lg_src,
    const int* __restrict__ lg_dst, int L) {
    int idx = blockIdx.x * blockDim.x + threadIdx.x;  // L*8
    if (idx >= L * 8) return;
    int l = idx >> 3, b = idx & 7;
    int src = lg_src[l], dst = lg_dst[l];
    float x1 = o[src * 3], y1 = o[src * 3 + 1], z1 = o[src * 3 + 2];
    float x2 = o[dst * 3], y2 = o[dst * 3 + 1], z2 = o[dst * 3 + 2];
    float dot = x1 * x2 + y1 * y2 + z1 * z2;
    float cx = y1 * z2 - z1 * y2;
    float cy = z1 * x2 - x1 * z2;
    float cz = x1 * y2 - y1 * x2;
    float cr2 = cx * cx + cy * cy + cz * cz;
    float ct = dot / sqrtf(dot * dot + cr2);
    ct = fminf(1.f, fmaxf(-1.f, ct));
    float c0 = 1.f, c1 = ct;
    const float* Pp = g_P + (size_t)src * 56 + b;
    float acc = c0 * Pp[0] + c1 * Pp[8];
#pragma unroll
    for (int s = 2; s < NS; ++s) {
        float c2 = 2.f * ct * c1 - c0;
        acc += c2 * Pp[s * 8];
        c0 = c1;
        c1 = c2;
    }
    g_sbf[idx] = acc;
}

// ---------------- mma.sync edge GEMM: CTA 256Mx128N, 8 warps, warp 64x64 ----------------
// 128 B of ldsm per mma (vs 256 previously) -> LDS-crossbar load halved.
// chunk 0..7 -> g_Yh (fp16), chunk 8 -> w (silu * rbf@W_rbf).
__global__ __launch_bounds__(256, 1) void mma_gemm(
    const float* __restrict__ rbf, const float* __restrict__ W_rbf,
    const float* __restrict__ b_m, float* __restrict__ w_out, int E) {
    extern __shared__ __half sm[];
    __half* Ah = sm;                       // 256 x PITCH
    __half* Bh = sm + 256 * PITCH;         // 128 x PITCH

    const int tid = threadIdx.x;
    const int lane = tid & 31, wid = tid >> 5;
    const int wm = wid >> 1, wn = wid & 1;   // 4m x 2n
    const int chunk = blockIdx.x;
    const int e0 = blockIdx.y * 256;

    // stage A: 256 rows x 16 uint4 = 4096; B: 128 rows x 16 = 2048
    {
        const uint4* sA = (const uint4*)(g_Ah + (size_t)e0 * 128);
        const uint4* sB = (const uint4*)(g_Bh + (size_t)chunk * 128 * 128);
#pragma unroll
        for (int it = 0; it < 16; ++it) {
            int idx = it * 256 + tid;
            int row = idx >> 4, v = idx & 15;
            *(uint4*)(Ah + row * PITCH + v * 8) = sA[idx];
        }
#pragma unroll
        for (int it = 0; it < 8; ++it) {
            int idx = it * 256 + tid;
            int row = idx >> 4, v = idx & 15;
            *(uint4*)(Bh + row * PITCH + v * 8) = sB[idx];
        }
    }
    __syncthreads();

    const int a_row = wm * 64 + (lane & 15);
    const int a_k = (lane >> 4) * 8;
    uint32_t ah_b = smem_u32(Ah) + (a_row * PITCH + a_k) * 2;
    const int b_row = wn * 64 + ((lane >> 4) & 1) * 8 + (lane & 7);
    const int b_k = ((lane >> 3) & 1) * 8;
    uint32_t bh_b = smem_u32(Bh) + (b_row * PITCH + b_k) * 2;

    float c[4][8][4];
#pragma unroll
    for (int mi = 0; mi < 4; ++mi)
#pragma unroll
        for (int ni = 0; ni < 8; ++ni)
#pragma unroll
            for (int q = 0; q < 4; ++q) c[mi][ni][q] = 0.f;

    for (int kt = 0; kt < 8; ++kt) {
        const uint32_t ko = kt * 32;
        uint32_t ah[4][4], bh[4][4];
#pragma unroll
        for (int mi = 0; mi < 4; ++mi)
            ldsm4(ah[mi], ah_b + mi * 16 * PITCH * 2 + ko);
#pragma unroll
        for (int g = 0; g < 4; ++g) ldsm4(bh[g], bh_b + g * 16 * PITCH * 2 + ko);
#pragma unroll
        for (int mi = 0; mi < 4; ++mi)
#pragma unroll
            for (int ni = 0; ni < 8; ++ni) {
                const uint32_t* bp = &bh[ni >> 1][(ni & 1) * 2];
                mma16816(c[mi][ni], ah[mi], bp);
            }
    }

    const int r_lo = lane >> 2;
    const int c_lo = (lane & 3) * 2;
    if (chunk < 8) {
#pragma unroll
        for (int mi = 0; mi < 4; ++mi) {
            int r0 = e0 + wm * 64 + mi * 16 + r_lo;
#pragma unroll
            for (int ni = 0; ni < 8; ++ni) {
                int col = chunk * 128 + wn * 64 + ni * 8 + c_lo;
                if (r0 < E)
                    *(__half2*)&g_Yh[(size_t)r0 * 1024 + col] =
                        __floats2half2_rn(c[mi][ni][0], c[mi][ni][1]);
                if (r0 + 8 < E)
                    *(__half2*)&g_Yh[(size_t)(r0 + 8) * 1024 + col] =
                        __floats2half2_rn(c[mi][ni][2], c[mi][ni][3]);
            }
        }
    } else {
#pragma unroll
        for (int mi = 0; mi < 4; ++mi) {
            int r0 = e0 + wm * 64 + mi * 16 + r_lo;
#pragma unroll
            for (int half = 0; half < 2; ++half) {
                int e = r0 + half * 8;
                if (e >= E) continue;
                float rb[NR];
#pragma unroll
                for (int q = 0; q < NR; ++q) rb[q] = rbf[e * NR + q];
#pragma unroll
                for (int ni = 0; ni < 8; ++ni) {
#pragma unroll
                    for (int p = 0; p < 2; ++p) {
                        int i = wn * 64 + ni * 8 + c_lo + p;
                        float h = c[mi][ni][half * 2 + p] + b_m[i];
                        float sg = h / (1.f + __expf(-h));
                        float rw = 0.f;
#pragma unroll
                        for (int q = 0; q < NR; ++q) rw += rb[q] * W_rbf[q * EMB + i];
                        w_out[(size_t)e * EMB + i] = rw * sg;
                    }
                }
            }
        }
    }
}

// ---------------- triplet kernel (R6 form): warp per dst edge ----------------
__global__ __launch_bounds__(256) void triplet_kernel(
    const int* __restrict__ lg_src, float* __restrict__ m_upd, int E) {
    const int warp = (blockIdx.x * blockDim.x + threadIdx.x) >> 5;
    const int lane = threadIdx.x & 31;
    if (warp >= E) return;
    const int e = warp;
    const int n = g_cnt[e];
    const int base = g_off[e];

    float x0 = 0.f, x1 = 0.f, x2 = 0.f, x3 = 0.f;

    auto accum = [&](int l, int src) {
        float4 s01 = *(const float4*)&g_sbf[(size_t)l * 8];
        float4 s23 = *(const float4*)&g_sbf[(size_t)l * 8 + 4];
        const uint4* yp = (const uint4*)(g_Yh + (size_t)src * 1024);
        uint4 v0 = yp[lane * 4 + 0];
        uint4 v1 = yp[lane * 4 + 1];
        uint4 v2 = yp[lane * 4 + 2];
        uint4 v3 = yp[lane * 4 + 3];
        float sb[8] = {s01.x, s01.y, s01.z, s01.w, s23.x, s23.y, s23.z, s23.w};
        const __half2* h0 = (const __half2*)&v0;
        const __half2* h1 = (const __half2*)&v1;
        const __half2* h2 = (const __half2*)&v2;
        const __half2* h3 = (const __half2*)&v3;
#pragma unroll
        for (int p = 0; p < 4; ++p) {
            float2 f0 = __half22float2(h0[p]);
            float2 f1 = __half22float2(h1[p]);
            float2 f2 = __half22float2(h2[p]);
            float2 f3 = __half22float2(h3[p]);
            x0 += sb[2 * p] * f0.x + sb[2 * p + 1] * f0.y;
            x1 += sb[2 * p] * f1.x + sb[2 * p + 1] * f1.y;
            x2 += sb[2 * p] * f2.x + sb[2 * p + 1] * f2.y;
            x3 += sb[2 * p] * f3.x + sb[2 * p + 1] * f3.y;
        }
    };

    int t = 0;
    for (; t + 2 <= n; t += 2) {
        int l0 = g_order[base + t];
        int l1 = g_order[base + t + 1];
        int s0 = lg_src[l0];
        int s1 = lg_src[l1];
        accum(l0, s0);
        accum(l1, s1);
    }
    if (t < n) {
        int l0 = g_order[base + t];
        accum(l0, lg_src[l0]);
    }

    ((float4*)m_upd)[(size_t)e * 32 + lane] = make_float4(x0, x1, x2, x3);
}

// ---------------- launch ----------------
extern "C" void kernel_launch(void* const* d_in, const int* in_sizes, int n_in,
                              void* d_out, int out_size) {
    const float* rbf     = (const float*)d_in[0];
    const float* m       = (const float*)d_in[1];
    const float* o       = (const float*)d_in[2];
    const int*   lg_src  = (const int*)d_in[3];
    const int*   lg_dst  = (const int*)d_in[4];
    const float* W_rbf   = (const float*)d_in[5];
    const float* W_m     = (const float*)d_in[6];
    const float* b_m     = (const float*)d_in[7];
    const float* W_sbf   = (const float*)d_in[8];
    const float* W_bilin = (const float*)d_in[9];

    const int E = in_sizes[1] / EMB;   // 100000
    const int L = in_sizes[3];         // 500000
    const int nblk = (E + 1023) / 1024;

    float* w_out = (float*)d_out;                    // [E,128]
    float* m_upd = w_out + (size_t)E * EMB;          // [E,128]

    // ncu captures the 4th launch -> mma_gemm stays there.
    prep_m<<<(EPAD * 128 + 255) / 256, 256>>>(m, E);                 // 1
    prep_B<<<(1152 * 128 + 255) / 256, 256>>>(W_bilin, W_m);         // 2
    prep_P<<<(E * 8 + 255) / 256, 256>>>(rbf, W_sbf, E);             // 3

    const int dynsmem = (256 + 128) * PITCH * 2;  // 104448 bytes
    cudaFuncSetAttribute(mma_gemm, cudaFuncAttributeMaxDynamicSharedMemorySize, dynsmem);
    dim3 g(9, (E + 255) / 256);
    mma_gemm<<<g, 256, dynsmem>>>(rbf, W_rbf, b_m, w_out, E);        // 4 <- profiled

    zero_cnt<<<(E + 255) / 256, 256>>>(E);                           // 5
    count_k<<<(L + 255) / 256, 256>>>(lg_dst, L);                    // 6
    scan1<<<nblk, 1024>>>(E);                                        // 7
    scan2<<<1, 128>>>(nblk);                                         // 8
    scan3<<<nblk, 1024>>>(E);                                        // 9
    scatter_k<<<(L + 255) / 256, 256>>>(lg_dst, L);                  // 10
    sbf_kernel<<<(L * 8 + 255) / 256, 256>>>(o, lg_src, lg_dst, L);  // 11

    triplet_kernel<<<(E * 32 + 255) / 256, 256>>>(lg_src, m_upd, E); // 12
}